// round 12
// baseline (speedup 1.0000x reference)
#include <cuda_runtime.h>
#include <cstdint>

// KANLayer: out[b] = sum_d ( b2[d] + sum_h w2[d,h]*tanh(w1[d,h]*x[b,d] + b1[d,h]) )
// Tabulated f_d: 192 bins over [-6.4,6.4], float2 (value, slope), transposed
// [bin][row] -> lane-indexed LDS conflict-free. x streamed into smem via
// cp.async.bulk (TMA queue) with a 2-stage mbarrier ring: consumers never LDG.

#define B_SIZE 65536
#define D_SIZE 256
#define H_SIZE 16
#define BINS   192
#define XSCALE 15.0f          /* BINS / 12.8 */
#define XOFF   96.0f          /* 6.4 * XSCALE */
#define CLMAX  191.999f

#define ROWS    32
#define NGROUPS (D_SIZE / ROWS)       /* 8 */
#define NSLICES 37
#define SPLIT   31                    /* slices < SPLIT take 14 chunks, rest 13 */
#define CHUNK_B 128                   /* b-rows per chunk */
#define THREADS 512                   /* 16 warps */

#define TAB_BYTES   (BINS * ROWS * 8)            /* 49152 */
#define CH_BYTES    (CHUNK_B * ROWS * 4)         /* 16384 */
#define MBAR_OFF    (TAB_BYTES + 2 * CH_BYTES)   /* 81920 */
#define SMEM_TOTAL  (MBAR_OFF + 64)

// transposed per group: [group][bin][row]
__device__ float2   g_tab[NGROUPS][BINS][ROWS];   // 384 KB (L2-resident)
__device__ float    g_partial[NGROUPS * B_SIZE];  // 2 MB
__device__ unsigned g_cnt[NSLICES];

__device__ __forceinline__ float ftanh(float z)
{
    float e = __expf(2.0f * z);
    return fmaf(-2.0f, __fdividef(1.0f, e + 1.0f), 1.0f);
}

__device__ __forceinline__ uint32_t smem_u32(const void* p)
{
    uint32_t a;
    asm("{ .reg .u64 t; cvta.to.shared.u64 t, %1; cvt.u32.u64 %0, t; }"
        : "=r"(a) : "l"(p));
    return a;
}

__device__ __forceinline__ void mbar_init(uint32_t m, uint32_t cnt)
{
    asm volatile("mbarrier.init.shared.b64 [%0], %1;" :: "r"(m), "r"(cnt) : "memory");
}
__device__ __forceinline__ void mbar_expect_tx(uint32_t m, uint32_t bytes)
{
    asm volatile("mbarrier.arrive.expect_tx.shared.b64 _, [%0], %1;"
                 :: "r"(m), "r"(bytes) : "memory");
}
__device__ __forceinline__ void mbar_arrive(uint32_t m)
{
    asm volatile("mbarrier.arrive.shared.b64 _, [%0];" :: "r"(m) : "memory");
}
__device__ __forceinline__ void mbar_wait(uint32_t m, uint32_t ph)
{
    asm volatile(
        "{\n\t.reg .pred P;\n"
        "W_%=:\n\t"
        "mbarrier.try_wait.parity.acquire.cta.shared::cta.b64 P, [%0], %1, 0x989680;\n\t"
        "@P bra.uni D_%=;\n\t"
        "bra.uni W_%=;\n"
        "D_%=:\n\t}"
        :: "r"(m), "r"(ph) : "memory");
}
__device__ __forceinline__ void bulk_g2s(uint32_t dst, const void* src,
                                         uint32_t bytes, uint32_t mbar)
{
    asm volatile(
        "cp.async.bulk.shared::cluster.global.mbarrier::complete_tx::bytes "
        "[%0], [%1], %2, [%3];"
        :: "r"(dst), "l"(src), "r"(bytes), "r"(mbar) : "memory");
}

// ---------------------------------------------------------------------------
// Kernel 1: build tables. CTA = feature d; thread t computes nodes t, t+1.
// ---------------------------------------------------------------------------
__global__ void __launch_bounds__(BINS) build_table(
    const float* __restrict__ w1, const float* __restrict__ b1,
    const float* __restrict__ w2, const float* __restrict__ b2)
{
    const int d = blockIdx.x;
    const int t = threadIdx.x;
    const int grp = d >> 5, row = d & 31;

    if (d == 0 && t < NSLICES) g_cnt[t] = 0;   // reset fused-reduce counters

    float lw1[H_SIZE], lb1[H_SIZE], lw2[H_SIZE];
#pragma unroll
    for (int k = 0; k < H_SIZE; k++) {
        lw1[k] = __ldg(&w1[d * H_SIZE + k]);
        lb1[k] = __ldg(&b1[d * H_SIZE + k]);
        lw2[k] = __ldg(&w2[d * H_SIZE + k]);
    }
    const float b2d = __ldg(&b2[d]);

    const float h = 12.8f / (float)BINS;
    float node[2];
#pragma unroll
    for (int j = 0; j < 2; j++) {
        float xv = fmaf((float)(t + j), h, -6.4f);
        float a0 = 0.f, a1 = 0.f, a2 = 0.f, a3 = 0.f;
#pragma unroll
        for (int k = 0; k < H_SIZE; k += 4) {
            a0 = fmaf(lw2[k],     ftanh(fmaf(lw1[k],     xv, lb1[k])),     a0);
            a1 = fmaf(lw2[k + 1], ftanh(fmaf(lw1[k + 1], xv, lb1[k + 1])), a1);
            a2 = fmaf(lw2[k + 2], ftanh(fmaf(lw1[k + 2], xv, lb1[k + 2])), a2);
            a3 = fmaf(lw2[k + 3], ftanh(fmaf(lw1[k + 3], xv, lb1[k + 3])), a3);
        }
        node[j] = b2d + ((a0 + a1) + (a2 + a3));
    }

    g_tab[grp][t][row] = make_float2(node[0], node[1] - node[0]);
}

// ---------------------------------------------------------------------------
// Kernel 2: main pass + fused final reduction.
// CTA = (group g, slice s), 512 threads. Producer: threads 0..127 bulk-copy
// row tid's 128B segment of each chunk into a 2-stage smem ring (full barrier
// count=128 via per-thread expect_tx; empty barrier count=512). Consumer:
// warp w handles 8 b-rows per chunk from smem; lookups conflict-free;
// butterfly reduce; last CTA per slice does the final 8-group sum.
// ---------------------------------------------------------------------------
__global__ void __launch_bounds__(THREADS, 2) kan_main(
    const float* __restrict__ x, float* __restrict__ out)
{
    extern __shared__ char smem[];
    float2* tab = (float2*)smem;                       // 48 KB
    char*   xb  = smem + TAB_BYTES;                    // 2 x 16 KB stages
    const uint32_t mb = smem_u32(smem) + MBAR_OFF;     // 4 mbarriers
    const uint32_t full0 = mb, full1 = mb + 8, emp0 = mb + 16, emp1 = mb + 24;

    const int bid = blockIdx.x;
    const int g = bid / NSLICES;
    const int s = bid - g * NSLICES;
    const int tid = threadIdx.x;

    if (tid == 0) {
        mbar_init(full0, 128); mbar_init(full1, 128);
        mbar_init(emp0, THREADS); mbar_init(emp1, THREADS);
    }

    {   // cooperative table copy (gmem layout already transposed)
        const float4* src = (const float4*)&g_tab[g][0][0];
        float4* dst = (float4*)tab;
#pragma unroll
        for (int i = tid; i < BINS * ROWS * 2 / 4; i += THREADS)
            dst[i] = src[i];
    }
    __syncthreads();   // barriers initialized + table ready

    const int nchunk = (s < SPLIT) ? 14 : 13;
    const int startc = (s < SPLIT) ? 14 * s : SPLIT * 14 + 13 * (s - SPLIT);

    const int warp = tid >> 5;
    const int lane = tid & 31;
    float* part = &g_partial[g * B_SIZE];
    const uint32_t xb_u32 = smem_u32(xb);

#pragma unroll 1
    for (int c = 0; c < nchunk; c++) {
        const int st = c & 1;
        const int u  = c >> 1;
        const uint32_t fullb = st ? full1 : full0;
        const uint32_t empb  = st ? emp1  : emp0;
        const int bb = (startc + c) * CHUNK_B;

        // -- producer: threads 0..127, one 128B row segment each --
        if (tid < CHUNK_B) {
            if (c >= 2) mbar_wait(empb, (u - 1) & 1);
            mbar_expect_tx(fullb, 128);
            const float* src = x + (size_t)(bb + tid) * D_SIZE + g * ROWS;
            bulk_g2s(xb_u32 + st * CH_BYTES + tid * 128, src, 128, fullb);
        }

        // -- consumer: wait data, compute 8 b-rows per warp --
        mbar_wait(fullb, u & 1);

        const float* xs = (const float*)(xb + st * CH_BYTES) + warp * 8 * ROWS;

        float v[8];
#pragma unroll
        for (int r = 0; r < 8; r++) {
            float xr = xs[r * ROWS + lane];
            float t  = fmaf(xr, XSCALE, XOFF);
            t        = fminf(fmaxf(t, 0.0f), CLMAX);
            int   i  = (int)t;
            float fr = t - (float)i;
            float2 e = tab[(i << 5) + lane];
            v[r] = fmaf(e.y, fr, e.x);
        }

        // butterfly transpose-reduce over 8 slots, then fold lane bits 3,4
#pragma unroll
        for (int k = 1; k <= 4; k <<= 1) {
            const int n = 8 / k;
            const bool up = (lane & k) != 0;
#pragma unroll
            for (int i2 = 0; i2 < n / 2; i2++) {
                float a = v[2 * i2], cc = v[2 * i2 + 1];
                float send = up ? a : cc;
                float r = __shfl_xor_sync(0xffffffffu, send, k);
                v[i2] = (up ? cc : a) + r;
            }
        }
        v[0] += __shfl_xor_sync(0xffffffffu, v[0], 8);
        v[0] += __shfl_xor_sync(0xffffffffu, v[0], 16);

        if (lane < 8) part[bb + warp * 8 + lane] = v[0];

        mbar_arrive(empb);   // this thread is done reading stage st
    }

    // ---- fused final reduction: last CTA of this slice sums the 8 groups ----
    __syncthreads();
    unsigned* flag = (unsigned*)tab;          // tab no longer needed
    if (tid == 0) {
        __threadfence();
        unsigned r = atomicAdd(&g_cnt[s], 1u);
        *flag = (r == NGROUPS - 1) ? 1u : 0u;
    }
    __syncthreads();
    if (*flag) {
        __threadfence();
        const int nb = nchunk * CHUNK_B;               // 1792 or 1664
        if (tid * 4 < nb) {
            const int base = startc * CHUNK_B + tid * 4;
            float4 sv = make_float4(0.f, 0.f, 0.f, 0.f);
#pragma unroll
            for (int gi = 0; gi < NGROUPS; gi++) {
                float4 p = *(const float4*)&g_partial[gi * B_SIZE + base];
                sv.x += p.x; sv.y += p.y; sv.z += p.z; sv.w += p.w;
            }
            *(float4*)&out[base] = sv;
        }
    }
}

// ---------------------------------------------------------------------------
extern "C" void kernel_launch(void* const* d_in, const int* in_sizes, int n_in,
                              void* d_out, int out_size)
{
    const float* x  = (const float*)d_in[0];
    const float* w1 = (const float*)d_in[1];
    const float* b1 = (const float*)d_in[2];
    const float* w2 = (const float*)d_in[3];
    const float* b2 = (const float*)d_in[4];
    float* out = (float*)d_out;

    cudaFuncSetAttribute(kan_main,
                         cudaFuncAttributeMaxDynamicSharedMemorySize, SMEM_TOTAL);

    build_table<<<D_SIZE, BINS>>>(w1, b1, w2, b2);
    kan_main<<<NGROUPS * NSLICES, THREADS, SMEM_TOTAL>>>(x, out);
}

// round 13
// speedup vs baseline: 1.7817x; 1.7817x over previous
#include <cuda_runtime.h>
#include <cstdint>

// KANLayer: out[b] = sum_d ( b2[d] + sum_h w2[d,h]*tanh(w1[d,h]*x[b,d] + b1[d,h]) )
// Tabulated f_d: 160 bins over [-6.4,6.4], float2 (value, slope), transposed
// [bin][row] -> lane-indexed LDS conflict-free. x prefetched into a per-warp
// 2-stage smem ring via cp.async.cg 16B (register-free, no barriers).

#define B_SIZE 65536
#define D_SIZE 256
#define H_SIZE 16
#define BINS   160
#define XSCALE 12.5f          /* BINS / 12.8 */
#define XOFF   80.0f
#define CLMAX  159.999f

#define ROWS    32
#define NGROUPS (D_SIZE / ROWS)       /* 8 */
#define NSLICES 55
#define SPLIT   17                    /* slices < SPLIT take 10 chunks, rest 9 */
#define CHUNK_B 128                   /* 8 warps x 16 b-rows */
#define MAIN_THREADS 256

#define TAB_BYTES  (BINS * ROWS * 8)          /* 40960 */
#define STAGE_B    2048                       /* 16 rows x 128B */
#define WBUF_B     (2 * STAGE_B)              /* per-warp ring */
#define XBUF_BYTES (8 * WBUF_B)               /* 32768 */
#define SMEM_TOTAL (TAB_BYTES + XBUF_BYTES)   /* 73728 */

// transposed per group: [group][bin][row]
__device__ float2   g_tab[NGROUPS][BINS][ROWS];   // 320 KB (L2-resident)
__device__ float    g_partial[NGROUPS * B_SIZE];  // 2 MB
__device__ unsigned g_cnt[NSLICES];

__device__ __forceinline__ float ftanh(float z)
{
    float e = __expf(2.0f * z);
    return fmaf(-2.0f, __fdividef(1.0f, e + 1.0f), 1.0f);
}

__device__ __forceinline__ uint32_t smem_u32(const void* p)
{
    uint32_t a;
    asm("{ .reg .u64 t; cvta.to.shared.u64 t, %1; cvt.u32.u64 %0, t; }"
        : "=r"(a) : "l"(p));
    return a;
}

// ---------------------------------------------------------------------------
// Kernel 1: build tables. CTA = feature d; thread t computes nodes t, t+1.
// ---------------------------------------------------------------------------
__global__ void __launch_bounds__(BINS) build_table(
    const float* __restrict__ w1, const float* __restrict__ b1,
    const float* __restrict__ w2, const float* __restrict__ b2)
{
    const int d = blockIdx.x;
    const int t = threadIdx.x;
    const int grp = d >> 5, row = d & 31;

    if (d == 0 && t < NSLICES) g_cnt[t] = 0;   // reset fused-reduce counters

    float lw1[H_SIZE], lb1[H_SIZE], lw2[H_SIZE];
#pragma unroll
    for (int k = 0; k < H_SIZE; k++) {
        lw1[k] = __ldg(&w1[d * H_SIZE + k]);
        lb1[k] = __ldg(&b1[d * H_SIZE + k]);
        lw2[k] = __ldg(&w2[d * H_SIZE + k]);
    }
    const float b2d = __ldg(&b2[d]);

    const float h = 12.8f / (float)BINS;
    float node[2];
#pragma unroll
    for (int j = 0; j < 2; j++) {
        float xv = fmaf((float)(t + j), h, -6.4f);
        float a0 = 0.f, a1 = 0.f, a2 = 0.f, a3 = 0.f;
#pragma unroll
        for (int k = 0; k < H_SIZE; k += 4) {
            a0 = fmaf(lw2[k],     ftanh(fmaf(lw1[k],     xv, lb1[k])),     a0);
            a1 = fmaf(lw2[k + 1], ftanh(fmaf(lw1[k + 1], xv, lb1[k + 1])), a1);
            a2 = fmaf(lw2[k + 2], ftanh(fmaf(lw1[k + 2], xv, lb1[k + 2])), a2);
            a3 = fmaf(lw2[k + 3], ftanh(fmaf(lw1[k + 3], xv, lb1[k + 3])), a3);
        }
        node[j] = b2d + ((a0 + a1) + (a2 + a3));
    }

    g_tab[grp][t][row] = make_float2(node[0], node[1] - node[0]);
}

// ---------------------------------------------------------------------------
// Kernel 2: main pass + fused final reduction.
// CTA = (group g, slice s). Lane = feature row. Per chunk (128 b), warp w
// covers rows w*16..w*16+15, staged via cp.async.cg (4x16B per tile) into a
// private 2-stage ring. Consumer: conflict-free LDS + butterfly reduce.
// ---------------------------------------------------------------------------
__global__ void __launch_bounds__(MAIN_THREADS, 3) kan_main(
    const float* __restrict__ x, float* __restrict__ out)
{
    extern __shared__ char smem[];
    float2* tab = (float2*)smem;               // 40 KB
    char*   xb  = smem + TAB_BYTES;            // 8 x (2 x 2KB) rings

    const int bid = blockIdx.x;
    const int g = bid / NSLICES;
    const int s = bid - g * NSLICES;
    const int tid  = threadIdx.x;
    const int warp = tid >> 5;
    const int lane = tid & 31;
    const int seg  = lane & 7;                 // 16B segment within a row
    const int rowq = lane >> 3;                // base row (0..3)

    const int nchunk = (s < SPLIT) ? 10 : 9;
    const int startc = (s < SPLIT) ? 10 * s : SPLIT * 10 + 9 * (s - SPLIT);

    char* wbuf = xb + warp * WBUF_B;
    const uint32_t wbase = smem_u32(wbuf) + (uint32_t)(rowq * 128 + seg * 16);
    const float* xsrc = x + g * ROWS + seg * 4;   // + (b)*D_SIZE per row

    // prefetch chunk c's 16 rows for this warp into stage st
#define PREFETCH(c, st)                                                       \
    do {                                                                      \
        const int bbase_ = (startc + (c)) * CHUNK_B + warp * 16 + rowq;       \
        uint32_t dst_ = wbase + (uint32_t)(st) * STAGE_B;                     \
        _Pragma("unroll")                                                     \
        for (int k = 0; k < 4; k++)                                           \
            asm volatile("cp.async.cg.shared.global [%0], [%1], 16;"          \
                         :: "r"(dst_ + k * (4u * 128u)),                      \
                            "l"(xsrc + (size_t)(bbase_ + k * 4) * D_SIZE)     \
                         : "memory");                                         \
        asm volatile("cp.async.commit_group;" ::: "memory");                  \
    } while (0)

    PREFETCH(0, 0);   // overlaps with the table copy below

    {   // cooperative table copy (gmem layout already transposed)
        const float4* src = (const float4*)&g_tab[g][0][0];
        float4* dst = (float4*)tab;
#pragma unroll
        for (int i = tid; i < BINS * ROWS * 2 / 4; i += MAIN_THREADS)
            dst[i] = src[i];
    }
    __syncthreads();

    float* part = &g_partial[g * B_SIZE];

#pragma unroll 1
    for (int c = 0; c < nchunk; c++) {
        const int st = c & 1;
        if (c + 1 < nchunk) {
            PREFETCH(c + 1, st ^ 1);
            asm volatile("cp.async.wait_group 1;" ::: "memory");
        } else {
            asm volatile("cp.async.wait_group 0;" ::: "memory");
        }

        const float* xs = (const float*)(wbuf + st * STAGE_B);
        const int bb = (startc + c) * CHUNK_B + warp * 16;

        float v[16];
#pragma unroll
        for (int j = 0; j < 16; j++) {
            float xr = xs[j * 32 + lane];
            float t  = fmaf(xr, XSCALE, XOFF);
            t        = fminf(fmaxf(t, 0.0f), CLMAX);
            int   i  = (int)t;
            float fr = t - (float)i;
            float2 e = tab[(i << 5) + lane];
            v[j] = fmaf(e.y, fr, e.x);
        }

        // butterfly transpose-reduce -> v[0] = sum over 32 lanes for b = bb+(lane&15)
#pragma unroll
        for (int k = 1; k <= 8; k <<= 1) {
            const int n = 16 / k;
            const bool up = (lane & k) != 0;
#pragma unroll
            for (int i2 = 0; i2 < n / 2; i2++) {
                float a = v[2 * i2], cc = v[2 * i2 + 1];
                float send = up ? a : cc;
                float r = __shfl_xor_sync(0xffffffffu, send, k);
                v[i2] = (up ? cc : a) + r;
            }
        }
        v[0] += __shfl_xor_sync(0xffffffffu, v[0], 16);

        if (lane < 16) part[bb + lane] = v[0];
    }
#undef PREFETCH

    // ---- fused final reduction: last CTA of this slice sums the 8 groups ----
    __syncthreads();
    unsigned* flag = (unsigned*)tab;          // tab no longer needed
    if (tid == 0) {
        __threadfence();
        unsigned r = atomicAdd(&g_cnt[s], 1u);
        *flag = (r == NGROUPS - 1) ? 1u : 0u;
    }
    __syncthreads();
    if (*flag) {
        __threadfence();
        const int nb = nchunk * CHUNK_B;               // 1280 or 1152
        for (int off = tid * 4; off < nb; off += MAIN_THREADS * 4) {
            const int base = startc * CHUNK_B + off;
            float4 sv = make_float4(0.f, 0.f, 0.f, 0.f);
#pragma unroll
            for (int gi = 0; gi < NGROUPS; gi++) {
                float4 p = *(const float4*)&g_partial[gi * B_SIZE + base];
                sv.x += p.x; sv.y += p.y; sv.z += p.z; sv.w += p.w;
            }
            *(float4*)&out[base] = sv;
        }
    }
}

// ---------------------------------------------------------------------------
extern "C" void kernel_launch(void* const* d_in, const int* in_sizes, int n_in,
                              void* d_out, int out_size)
{
    const float* x  = (const float*)d_in[0];
    const float* w1 = (const float*)d_in[1];
    const float* b1 = (const float*)d_in[2];
    const float* w2 = (const float*)d_in[3];
    const float* b2 = (const float*)d_in[4];
    float* out = (float*)d_out;

    cudaFuncSetAttribute(kan_main,
                         cudaFuncAttributeMaxDynamicSharedMemorySize, SMEM_TOTAL);

    build_table<<<D_SIZE, BINS>>>(w1, b1, w2, b2);
    kan_main<<<NGROUPS * NSLICES, MAIN_THREADS, SMEM_TOTAL>>>(x, out);
}